// round 1
// baseline (speedup 1.0000x reference)
#include <cuda_runtime.h>
#include <math.h>

// Problem dims
#define Bsz 256
#define Slen 128
#define Fdim 128
#define Hdim 512
#define Cdim 64
#define Ldim 16
#define G4  2048           // 4*H
#define KTOT 640           // H + F (fused [h | x_t] GEMM)

// Scratch (device globals; no allocations allowed)
__device__ float g_h[2][Bsz * Hdim];     // ping-pong hidden state
__device__ float g_c[Bsz * Hdim];        // cell state
__device__ float g_tmp[Bsz * Hdim];      // context-gate hidden
__device__ float g_ctx[Bsz * 3 * Hdim];  // sigmoid context gates [ci|cf|co]

__device__ __forceinline__ float sigmoidf(float x) {
    return 1.0f / (1.0f + expf(-x));
}

// ---------------------------------------------------------------------------
// Zero h[0] and c
// ---------------------------------------------------------------------------
__global__ void zero_state_kernel() {
    int i = blockIdx.x * blockDim.x + threadIdx.x;
    if (i < Bsz * Hdim) {
        g_h[0][i] = 0.0f;
        g_c[i] = 0.0f;
    }
}

// ---------------------------------------------------------------------------
// Context gate stage 1: tmp = relu(context @ cg_w1 + cg_b1)   [256,512]
// one block per batch row, 128 threads, 4 outputs/thread
// ---------------------------------------------------------------------------
__global__ __launch_bounds__(128) void ctx1_kernel(
    const float* __restrict__ context,   // [256,64]
    const float* __restrict__ cg_w1,     // [64,512]
    const float* __restrict__ cg_b1)     // [512]
{
    __shared__ float cr[Cdim];
    int b = blockIdx.x;
    for (int k = threadIdx.x; k < Cdim; k += 128) cr[k] = context[b * Cdim + k];
    __syncthreads();
#pragma unroll
    for (int j = 0; j < 4; j++) {
        int n = threadIdx.x + j * 128;
        float s = cg_b1[n];
        for (int k = 0; k < Cdim; k++) s += cr[k] * cg_w1[k * Hdim + n];
        g_tmp[b * Hdim + n] = fmaxf(s, 0.0f);
    }
}

// ---------------------------------------------------------------------------
// Context gate stage 2: ctx = sigmoid(tmp @ cg_w2 + cg_b2)    [256,1536]
// one block per batch row, 256 threads, 6 outputs/thread
// ---------------------------------------------------------------------------
__global__ __launch_bounds__(256) void ctx2_kernel(
    const float* __restrict__ cg_w2,     // [512,1536]
    const float* __restrict__ cg_b2)     // [1536]
{
    __shared__ float tr[Hdim];
    int b = blockIdx.x;
    for (int k = threadIdx.x; k < Hdim; k += 256) tr[k] = g_tmp[b * Hdim + k];
    __syncthreads();
#pragma unroll
    for (int j = 0; j < 6; j++) {
        int n = threadIdx.x + j * 256;
        float s = cg_b2[n];
        for (int k = 0; k < Hdim; k++) s += tr[k] * cg_w2[k * 3 * Hdim + n];
        g_ctx[b * 3 * Hdim + n] = sigmoidf(s);
    }
}

// ---------------------------------------------------------------------------
// One LSTM step, fully fused:
//   gates[256,2048] = [h | x_t] @ [W_hh ; W_ih] + (b_ih + b_hh)
//   then context-gated LSTM update in the epilogue.
// CTA tile: 32 batch rows x 32 H-columns (x 4 gate groups) ; K loop = 640.
// grid (16, 8), 128 threads. Each thread: 8 rows x 4 gates = 32 accumulators.
// ---------------------------------------------------------------------------
__global__ __launch_bounds__(128) void step_kernel(
    const float* __restrict__ x,      // [256,128,128]
    const float* __restrict__ W_ih,   // [128,2048]
    const float* __restrict__ b_ih,   // [2048]
    const float* __restrict__ W_hh,   // [512,2048]
    const float* __restrict__ b_hh,   // [2048]
    int t)
{
    const int tx = threadIdx.x & 31;     // H-column within tile
    const int ty = threadIdx.x >> 5;     // 0..3 -> 8 batch rows each
    const int h0 = blockIdx.x * 32;      // H tile offset
    const int b0 = blockIdx.y * 32;      // batch tile offset

    const float* __restrict__ h_in = g_h[t & 1];
    float* __restrict__ h_out = g_h[(t + 1) & 1];

    __shared__ float As[32][33];    // [kk][row] (padded)
    __shared__ float Bs[32][128];   // [kk][n] ; n = gate*32 + hcol

    float acc[8][4];
#pragma unroll
    for (int r = 0; r < 8; r++)
#pragma unroll
        for (int g = 0; g < 4; g++) acc[r][g] = 0.0f;

    for (int k0 = 0; k0 < KTOT; k0 += 32) {
        // --- load A tile: [h | x_t] rows b0..b0+31, k-slice k0..k0+31
#pragma unroll
        for (int i = 0; i < 8; i++) {
            int idx = i * 128 + threadIdx.x;
            int r = idx >> 5;
            int kk = idx & 31;
            int k = k0 + kk;
            float v;
            if (k < Hdim) v = h_in[(b0 + r) * Hdim + k];
            else          v = x[(size_t)(b0 + r) * (Slen * Fdim) + t * Fdim + (k - Hdim)];
            As[kk][r] = v;
        }
        // --- load B tile: Wcat rows k0..k0+31, cols {g*512 + h0 + 0..31}
#pragma unroll
        for (int i = 0; i < 32; i++) {
            int kk = i;
            int n = threadIdx.x;
            int g = n >> 5;
            int col = g * Hdim + h0 + (n & 31);
            int k = k0 + kk;
            float v = (k < Hdim) ? W_hh[k * G4 + col]
                                 : W_ih[(k - Hdim) * G4 + col];
            Bs[kk][n] = v;
        }
        __syncthreads();

#pragma unroll
        for (int kk = 0; kk < 32; kk++) {
            float bv[4], a[8];
#pragma unroll
            for (int g = 0; g < 4; g++) bv[g] = Bs[kk][tx + 32 * g];
#pragma unroll
            for (int r = 0; r < 8; r++) a[r] = As[kk][ty * 8 + r];
#pragma unroll
            for (int r = 0; r < 8; r++)
#pragma unroll
                for (int g = 0; g < 4; g++) acc[r][g] += a[r] * bv[g];
        }
        __syncthreads();
    }

    // --- fused LSTM epilogue
    const int hcol = h0 + tx;
    const float bi = b_ih[hcol]            + b_hh[hcol];
    const float bf = b_ih[Hdim + hcol]     + b_hh[Hdim + hcol];
    const float bg = b_ih[2 * Hdim + hcol] + b_hh[2 * Hdim + hcol];
    const float bo = b_ih[3 * Hdim + hcol] + b_hh[3 * Hdim + hcol];

#pragma unroll
    for (int r = 0; r < 8; r++) {
        int b = b0 + ty * 8 + r;
        const float* cx = g_ctx + (size_t)b * 3 * Hdim;
        float iv = sigmoidf(acc[r][0] + bi) * cx[hcol];
        float fv = sigmoidf(acc[r][1] + bf) * cx[Hdim + hcol];
        float gv = tanhf(acc[r][2] + bg);
        float ov = sigmoidf(acc[r][3] + bo) * cx[2 * Hdim + hcol];
        float c = fv * g_c[b * Hdim + hcol] + iv * gv;
        g_c[b * Hdim + hcol] = c;
        h_out[b * Hdim + hcol] = ov * tanhf(c);
    }
}

// ---------------------------------------------------------------------------
// VAE head: mu, log_var, z, decoder. One block per batch row.
// Final h lives in g_h[0] (t runs 0..127, so last h_out index = (127+1)&1 = 0).
// out layout: recon_x [256*128] | mu [256*16] | log_var [256*16]
// ---------------------------------------------------------------------------
__global__ __launch_bounds__(128) void head_kernel(
    const float* __restrict__ eps,     // [256,16]
    const float* __restrict__ mu_w,    // [512,16]
    const float* __restrict__ mu_b,    // [16]
    const float* __restrict__ lv_w,    // [512,16]
    const float* __restrict__ lv_b,    // [16]
    const float* __restrict__ dec_w1,  // [16,512]
    const float* __restrict__ dec_b1,  // [512]
    const float* __restrict__ dec_w2,  // [512,128]
    const float* __restrict__ dec_b2,  // [128]
    float* __restrict__ out)
{
    __shared__ float hrow[Hdim];
    __shared__ float zv[Ldim];
    __shared__ float d1[Hdim];
    int b = blockIdx.x;
    const float* h = g_h[0] + (size_t)b * Hdim;

    for (int k = threadIdx.x; k < Hdim; k += 128) hrow[k] = h[k];
    __syncthreads();

    if (threadIdx.x < Ldim) {
        int j = threadIdx.x;
        float m = mu_b[j];
        for (int k = 0; k < Hdim; k++) m += hrow[k] * mu_w[k * Ldim + j];
        out[Bsz * Fdim + b * Ldim + j] = m;  // mu
        float lv = lv_b[j];
        for (int k = 0; k < Hdim; k++) lv += hrow[k] * lv_w[k * Ldim + j];
        out[Bsz * Fdim + Bsz * Ldim + b * Ldim + j] = lv;  // log_var
        zv[j] = m + eps[b * Ldim + j] * expf(0.5f * lv);
    }
    __syncthreads();

    for (int n = threadIdx.x; n < Hdim; n += 128) {
        float s = dec_b1[n];
#pragma unroll
        for (int k = 0; k < Ldim; k++) s += zv[k] * dec_w1[k * Hdim + n];
        d1[n] = fmaxf(s, 0.0f);
    }
    __syncthreads();

    {
        int n = threadIdx.x;  // 0..127
        float s = dec_b2[n];
        for (int k = 0; k < Hdim; k++) s += d1[k] * dec_w2[k * Fdim + n];
        out[(size_t)b * Fdim + n] = s;  // recon_x
    }
}

// ---------------------------------------------------------------------------
extern "C" void kernel_launch(void* const* d_in, const int* in_sizes, int n_in,
                              void* d_out, int out_size)
{
    const float* x       = (const float*)d_in[0];
    const float* context = (const float*)d_in[1];
    const float* eps     = (const float*)d_in[2];
    const float* W_ih    = (const float*)d_in[3];
    const float* b_ih    = (const float*)d_in[4];
    const float* W_hh    = (const float*)d_in[5];
    const float* b_hh    = (const float*)d_in[6];
    const float* cg_w1   = (const float*)d_in[7];
    const float* cg_b1   = (const float*)d_in[8];
    const float* cg_w2   = (const float*)d_in[9];
    const float* cg_b2   = (const float*)d_in[10];
    const float* mu_w    = (const float*)d_in[11];
    const float* mu_b    = (const float*)d_in[12];
    const float* lv_w    = (const float*)d_in[13];
    const float* lv_b    = (const float*)d_in[14];
    const float* dec_w1  = (const float*)d_in[15];
    const float* dec_b1  = (const float*)d_in[16];
    const float* dec_w2  = (const float*)d_in[17];
    const float* dec_b2  = (const float*)d_in[18];
    float* out = (float*)d_out;

    zero_state_kernel<<<(Bsz * Hdim + 255) / 256, 256>>>();
    ctx1_kernel<<<Bsz, 128>>>(context, cg_w1, cg_b1);
    ctx2_kernel<<<Bsz, 256>>>(cg_w2, cg_b2);

    dim3 sgrid(Hdim / 32, Bsz / 32);   // (16, 8)
    for (int t = 0; t < Slen; t++) {
        step_kernel<<<sgrid, 128>>>(x, W_ih, b_ih, W_hh, b_hh, t);
    }

    head_kernel<<<Bsz, 128>>>(eps, mu_w, mu_b, lv_w, lv_b,
                              dec_w1, dec_b1, dec_w2, dec_b2, out);
}

// round 2
// speedup vs baseline: 1.6683x; 1.6683x over previous
#include <cuda_runtime.h>
#include <math.h>

// Problem dims
#define Bsz 256
#define Slen 128
#define Fdim 128
#define Hdim 512
#define Cdim 64
#define Ldim 16
#define G4  2048           // 4*H
#define KTOT 640           // H + F (fused [h | x_t] GEMM)
#define NCHUNK 20          // 640 / 32

// Scratch (device globals; no allocations allowed)
__device__ float g_h[2][Bsz * Hdim];     // ping-pong hidden state
__device__ float g_c[Bsz * Hdim];        // cell state
__device__ float g_tmp[Bsz * Hdim];      // context-gate hidden
__device__ float g_ctx[Bsz * 3 * Hdim];  // sigmoid context gates [ci|cf|co]

__device__ __forceinline__ float sigmoidf(float x) {
    return 1.0f / (1.0f + expf(-x));
}

// ---------------------------------------------------------------------------
__global__ void zero_state_kernel() {
    int i = blockIdx.x * blockDim.x + threadIdx.x;
    if (i < Bsz * Hdim) {
        g_h[0][i] = 0.0f;
        g_c[i] = 0.0f;
    }
}

// ---------------------------------------------------------------------------
// Context gate stage 1: tmp = relu(context @ cg_w1 + cg_b1)   [256,512]
// ---------------------------------------------------------------------------
__global__ __launch_bounds__(128) void ctx1_kernel(
    const float* __restrict__ context,   // [256,64]
    const float* __restrict__ cg_w1,     // [64,512]
    const float* __restrict__ cg_b1)     // [512]
{
    __shared__ float cr[Cdim];
    int b = blockIdx.x;
    for (int k = threadIdx.x; k < Cdim; k += 128) cr[k] = context[b * Cdim + k];
    __syncthreads();
#pragma unroll
    for (int j = 0; j < 4; j++) {
        int n = threadIdx.x + j * 128;
        float s = cg_b1[n];
        for (int k = 0; k < Cdim; k++) s += cr[k] * cg_w1[k * Hdim + n];
        g_tmp[b * Hdim + n] = fmaxf(s, 0.0f);
    }
}

// ---------------------------------------------------------------------------
// Context gate stage 2: ctx = sigmoid(tmp @ cg_w2 + cg_b2)    [256,1536]
// ---------------------------------------------------------------------------
__global__ __launch_bounds__(256) void ctx2_kernel(
    const float* __restrict__ cg_w2,     // [512,1536]
    const float* __restrict__ cg_b2)     // [1536]
{
    __shared__ float tr[Hdim];
    int b = blockIdx.x;
    for (int k = threadIdx.x; k < Hdim; k += 256) tr[k] = g_tmp[b * Hdim + k];
    __syncthreads();
#pragma unroll
    for (int j = 0; j < 6; j++) {
        int n = threadIdx.x + j * 256;
        float s = cg_b2[n];
        for (int k = 0; k < Hdim; k++) s += tr[k] * cg_w2[k * 3 * Hdim + n];
        g_ctx[b * 3 * Hdim + n] = sigmoidf(s);
    }
}

// ---------------------------------------------------------------------------
// Fused LSTM step. Tile: 32 batch x (16 hcol x 4 gates). grid (32,8)=256 CTAs.
// 128 threads, 16 accumulators each. K=640 in 20 chunks of 32, double-buffered.
// ---------------------------------------------------------------------------
__device__ __forceinline__ void ldg_tiles(
    const float* __restrict__ h_in, const float* __restrict__ x,
    const float* __restrict__ W_hh, const float* __restrict__ W_ih,
    int t, int b0, int h0, int k0, int tid, float4 ra[2], float4 rb[4])
{
    if (k0 < Hdim) {
#pragma unroll
        for (int i = 0; i < 2; i++) {
            int idx = i * 128 + tid, r = idx >> 3, q = idx & 7;
            ra[i] = *(const float4*)&h_in[(b0 + r) * Hdim + k0 + q * 4];
        }
#pragma unroll
        for (int i = 0; i < 4; i++) {
            int idx = i * 128 + tid, kk = idx >> 4, f = idx & 15;
            int g = f >> 2, hq = f & 3;
            rb[i] = *(const float4*)&W_hh[(k0 + kk) * G4 + g * Hdim + h0 + hq * 4];
        }
    } else {
        int kx = k0 - Hdim;
#pragma unroll
        for (int i = 0; i < 2; i++) {
            int idx = i * 128 + tid, r = idx >> 3, q = idx & 7;
            ra[i] = *(const float4*)&x[((size_t)(b0 + r) * Slen + t) * Fdim + kx + q * 4];
        }
#pragma unroll
        for (int i = 0; i < 4; i++) {
            int idx = i * 128 + tid, kk = idx >> 4, f = idx & 15;
            int g = f >> 2, hq = f & 3;
            rb[i] = *(const float4*)&W_ih[(kx + kk) * G4 + g * Hdim + h0 + hq * 4];
        }
    }
}

__device__ __forceinline__ void sts_tiles(
    float (*__restrict__ As)[36], float* __restrict__ Bs,
    int tid, const float4 ra[2], const float4 rb[4])
{
#pragma unroll
    for (int i = 0; i < 2; i++) {
        int idx = i * 128 + tid, r = idx >> 3, q = idx & 7;
        *(float4*)&As[r][q * 4] = ra[i];
    }
#pragma unroll
    for (int i = 0; i < 4; i++) {
        int idx = i * 128 + tid, kk = idx >> 4, f = idx & 15;
        int g = f >> 2, hq = f & 3;
        float* brow = Bs + kk * 72;
        brow[(hq * 4 + 0) * 4 + g] = rb[i].x;
        brow[(hq * 4 + 1) * 4 + g] = rb[i].y;
        brow[(hq * 4 + 2) * 4 + g] = rb[i].z;
        brow[(hq * 4 + 3) * 4 + g] = rb[i].w;
    }
}

__global__ __launch_bounds__(128) void step_kernel(
    const float* __restrict__ x,      // [256,128,128]
    const float* __restrict__ W_ih,   // [128,2048]
    const float* __restrict__ b_ih,   // [2048]
    const float* __restrict__ W_hh,   // [512,2048]
    const float* __restrict__ b_hh,   // [2048]
    int t)
{
    __shared__ float As[2][32][36];   // [buf][row][kk], pad 36 -> STS.128/LDS aligned
    __shared__ float Bs[2][32 * 72];  // [buf][kk][hc*4+g], pad 72 -> LDS.128 per hc

    const int tid = threadIdx.x;
    const int hc = tid & 15;          // h-column within tile
    const int rg = tid >> 4;          // row group (0..7), 4 rows each
    const int r0 = rg * 4;
    const int h0 = blockIdx.x * 16;
    const int b0 = blockIdx.y * 32;

    const float* __restrict__ h_in = g_h[t & 1];
    float* __restrict__ h_out = g_h[(t + 1) & 1];

    float acc[4][4];
#pragma unroll
    for (int r = 0; r < 4; r++)
#pragma unroll
        for (int g = 0; g < 4; g++) acc[r][g] = 0.0f;

    float4 ra[2], rb[4];
    ldg_tiles(h_in, x, W_hh, W_ih, t, b0, h0, 0, tid, ra, rb);
    sts_tiles(As[0], Bs[0], tid, ra, rb);
    __syncthreads();

    for (int c = 0; c < NCHUNK; c++) {
        const int buf = c & 1;
        if (c + 1 < NCHUNK)
            ldg_tiles(h_in, x, W_hh, W_ih, t, b0, h0, (c + 1) * 32, tid, ra, rb);

        const float (*__restrict__ Asb)[36] = As[buf];
        const float* __restrict__ Bsb = Bs[buf];
#pragma unroll
        for (int kk = 0; kk < 32; kk++) {
            float4 bq = *(const float4*)&Bsb[kk * 72 + hc * 4];
            float a0 = Asb[r0 + 0][kk];
            float a1 = Asb[r0 + 1][kk];
            float a2 = Asb[r0 + 2][kk];
            float a3 = Asb[r0 + 3][kk];
            acc[0][0] += a0 * bq.x; acc[0][1] += a0 * bq.y;
            acc[0][2] += a0 * bq.z; acc[0][3] += a0 * bq.w;
            acc[1][0] += a1 * bq.x; acc[1][1] += a1 * bq.y;
            acc[1][2] += a1 * bq.z; acc[1][3] += a1 * bq.w;
            acc[2][0] += a2 * bq.x; acc[2][1] += a2 * bq.y;
            acc[2][2] += a2 * bq.z; acc[2][3] += a2 * bq.w;
            acc[3][0] += a3 * bq.x; acc[3][1] += a3 * bq.y;
            acc[3][2] += a3 * bq.z; acc[3][3] += a3 * bq.w;
        }

        if (c + 1 < NCHUNK)
            sts_tiles(As[buf ^ 1], Bs[buf ^ 1], tid, ra, rb);
        __syncthreads();
    }

    // --- fused LSTM epilogue
    const int hcol = h0 + hc;
    const float bi = b_ih[hcol]            + b_hh[hcol];
    const float bf = b_ih[Hdim + hcol]     + b_hh[Hdim + hcol];
    const float bg = b_ih[2 * Hdim + hcol] + b_hh[2 * Hdim + hcol];
    const float bo = b_ih[3 * Hdim + hcol] + b_hh[3 * Hdim + hcol];

#pragma unroll
    for (int r = 0; r < 4; r++) {
        int b = b0 + r0 + r;
        const float* cx = g_ctx + (size_t)b * 3 * Hdim;
        float iv = sigmoidf(acc[r][0] + bi) * cx[hcol];
        float fv = sigmoidf(acc[r][1] + bf) * cx[Hdim + hcol];
        float gv = tanhf(acc[r][2] + bg);
        float ov = sigmoidf(acc[r][3] + bo) * cx[2 * Hdim + hcol];
        float cc = fv * g_c[b * Hdim + hcol] + iv * gv;
        g_c[b * Hdim + hcol] = cc;
        h_out[b * Hdim + hcol] = ov * tanhf(cc);
    }
}

// ---------------------------------------------------------------------------
// VAE head. Final h lives in g_h[0] ((127+1)&1 = 0).
// out layout: recon_x [256*128] | mu [256*16] | log_var [256*16]
// ---------------------------------------------------------------------------
__global__ __launch_bounds__(128) void head_kernel(
    const float* __restrict__ eps,     // [256,16]
    const float* __restrict__ mu_w,    // [512,16]
    const float* __restrict__ mu_b,    // [16]
    const float* __restrict__ lv_w,    // [512,16]
    const float* __restrict__ lv_b,    // [16]
    const float* __restrict__ dec_w1,  // [16,512]
    const float* __restrict__ dec_b1,  // [512]
    const float* __restrict__ dec_w2,  // [512,128]
    const float* __restrict__ dec_b2,  // [128]
    float* __restrict__ out)
{
    __shared__ float hrow[Hdim];
    __shared__ float zv[Ldim];
    __shared__ float d1[Hdim];
    int b = blockIdx.x;
    const float* h = g_h[0] + (size_t)b * Hdim;

    for (int k = threadIdx.x; k < Hdim; k += 128) hrow[k] = h[k];
    __syncthreads();

    if (threadIdx.x < Ldim) {
        int j = threadIdx.x;
        float m = mu_b[j];
        for (int k = 0; k < Hdim; k++) m += hrow[k] * mu_w[k * Ldim + j];
        out[Bsz * Fdim + b * Ldim + j] = m;  // mu
        float lv = lv_b[j];
        for (int k = 0; k < Hdim; k++) lv += hrow[k] * lv_w[k * Ldim + j];
        out[Bsz * Fdim + Bsz * Ldim + b * Ldim + j] = lv;  // log_var
        zv[j] = m + eps[b * Ldim + j] * expf(0.5f * lv);
    }
    __syncthreads();

    for (int n = threadIdx.x; n < Hdim; n += 128) {
        float s = dec_b1[n];
#pragma unroll
        for (int k = 0; k < Ldim; k++) s += zv[k] * dec_w1[k * Hdim + n];
        d1[n] = fmaxf(s, 0.0f);
    }
    __syncthreads();

    {
        int n = threadIdx.x;  // 0..127
        float s = dec_b2[n];
        for (int k = 0; k < Hdim; k++) s += d1[k] * dec_w2[k * Fdim + n];
        out[(size_t)b * Fdim + n] = s;  // recon_x
    }
}

// ---------------------------------------------------------------------------
extern "C" void kernel_launch(void* const* d_in, const int* in_sizes, int n_in,
                              void* d_out, int out_size)
{
    const float* x       = (const float*)d_in[0];
    const float* context = (const float*)d_in[1];
    const float* eps     = (const float*)d_in[2];
    const float* W_ih    = (const float*)d_in[3];
    const float* b_ih    = (const float*)d_in[4];
    const float* W_hh    = (const float*)d_in[5];
    const float* b_hh    = (const float*)d_in[6];
    const float* cg_w1   = (const float*)d_in[7];
    const float* cg_b1   = (const float*)d_in[8];
    const float* cg_w2   = (const float*)d_in[9];
    const float* cg_b2   = (const float*)d_in[10];
    const float* mu_w    = (const float*)d_in[11];
    const float* mu_b    = (const float*)d_in[12];
    const float* lv_w    = (const float*)d_in[13];
    const float* lv_b    = (const float*)d_in[14];
    const float* dec_w1  = (const float*)d_in[15];
    const float* dec_b1  = (const float*)d_in[16];
    const float* dec_w2  = (const float*)d_in[17];
    const float* dec_b2  = (const float*)d_in[18];
    float* out = (float*)d_out;

    zero_state_kernel<<<(Bsz * Hdim + 255) / 256, 256>>>();
    ctx1_kernel<<<Bsz, 128>>>(context, cg_w1, cg_b1);
    ctx2_kernel<<<Bsz, 256>>>(cg_w2, cg_b2);

    dim3 sgrid(32, 8);   // (H-col tiles, batch tiles)
    for (int t = 0; t < Slen; t++) {
        step_kernel<<<sgrid, 128>>>(x, W_ih, b_ih, W_hh, b_hh, t);
    }

    head_kernel<<<Bsz, 128>>>(eps, mu_w, mu_b, lv_w, lv_b,
                              dec_w1, dec_b1, dec_w2, dec_b2, out);
}